// round 12
// baseline (speedup 1.0000x reference)
#include <cuda_runtime.h>

#define SS 17
#define AA 5
#define CC 20
#define BIMG 256
#define GG 32
#define HW (SS*SS)          // 289
#define NPA (HW*AA)         // 1445
#define NTHREADS 128
#define NWARPS (NTHREADS/32)
#define SPLIT 6             // CTAs per image
#define GRID (BIMG*SPLIT)   // 1536
#define CHUNK ((NPA + SPLIT - 1) / SPLIT)   // 241 (<= 2*NTHREADS: two slots/thread)

__device__ float    g_sum;      // zero at load; reset by last CTA each launch
__device__ unsigned g_ticket;   // zero at load; atomicInc wraps back to 0 each launch

__global__ __launch_bounds__(NTHREADS, 8)
void yolo_loss_kernel(const float* __restrict__ bbox_pred,
                      const float* __restrict__ iou_pred,
                      const float* __restrict__ score_pred,
                      const float* __restrict__ targets,
                      const float* __restrict__ anchors,
                      float* __restrict__ out)
{
    const int blk  = blockIdx.x;
    const int b    = blk / SPLIT;
    const int part = blk - b * SPLIT;
    const int tid  = threadIdx.x;

    __shared__ float4 gbox[GG];      // GT corners in cell units (x17)
    __shared__ float  garea[GG];     // (17w)*(17h)
    __shared__ float  thr06[GG];     // 0.6 * garea
    __shared__ float4 tarv[GG];      // off_x, off_y, w, h (original units)
    __shared__ int    gcls[GG];
    __shared__ short  selmap[NPA];
    __shared__ float  anc[AA][2];    // anchors / 17
    __shared__ float  red[NWARPS];

    const int start = part * CHUNK;
    const int end   = (start + CHUNK < NPA) ? start + CHUNK : NPA;

    for (int i = start + tid; i < end; i += NTHREADS) selmap[i] = -1;
    if (tid < AA) {
        anc[tid][0] = anchors[tid*2+0] / 17.0f;
        anc[tid][1] = anchors[tid*2+1] / 17.0f;
    }
    __syncthreads();

    if (tid < GG) {
        const float* t = targets + ((size_t)b*GG + tid)*6;
        int   cls = (int)t[1];
        float x1 = t[2], y1 = t[3], x2 = t[4], y2 = t[5];
        gbox[tid] = make_float4(x1*17.0f, y1*17.0f, x2*17.0f, y2*17.0f);
        float w = x2 - x1, h = y2 - y1;
        float ar17 = (17.0f*w) * (17.0f*h);
        garea[tid] = ar17;
        thr06[tid] = 0.6f * ar17;
        float cxs = (x1 + x2) * 0.5f * 17.0f;
        float cys = (y1 + y2) * 0.5f * 17.0f;
        int ci = (int)floorf(cxs), cj = (int)floorf(cys);
        tarv[tid] = make_float4(cxs - (float)ci, cys - (float)cj, w, h);
        gcls[tid] = cls;
        // anchor argmax (first-max tiebreak)
        int best_a = 0; float best = -1.0f;
        float ar = w * h;
        #pragma unroll
        for (int a = 0; a < AA; a++) {
            float aw = anc[a][0], ah = anc[a][1];
            float inter = fminf(aw, w) * fminf(ah, h);
            float aiou  = inter / (aw*ah + ar - inter);
            if (aiou > best) { best = aiou; best_a = a; }
        }
        int cell = ci * SS + cj;
        selmap[cell*AA + best_a] = (short)tid;  // out-of-range writes never read
    }
    __syncthreads();

    const float* bb = bbox_pred  + (size_t)b * NPA * 4;
    const float* ip = iou_pred   + (size_t)b * NPA;
    const float* sp = score_pred + (size_t)b * NPA * CC;

    float acc = 0.0f;

    // two slots per thread, straight-line
    int  idx0 = start + tid;
    int  idx1 = start + NTHREADS + tid;
    bool v0 = idx0 < end;
    bool v1 = idx1 < end;
    int  s0 = v0 ? idx0 : start;
    int  s1 = v1 ? idx1 : start;

    float4 p0 = reinterpret_cast<const float4*>(bb)[s0];
    float4 p1 = reinterpret_cast<const float4*>(bb)[s1];

    int hw0 = s0 / AA, a0 = s0 - hw0*AA, i0 = hw0 / SS, j0 = hw0 - i0*SS;
    int hw1 = s1 / AA, a1 = s1 - hw1*AA, i1 = hw1 / SS, j1 = hw1 - i1*SS;

    float aw0 = p0.z * anc[a0][0], ah0 = p0.w * anc[a0][1];
    float qx1_0 = p0.x + (float)i0 - 0.5f*aw0, qx2_0 = p0.x + (float)i0 + 0.5f*aw0;
    float qy1_0 = p0.y + (float)j0 - 0.5f*ah0, qy2_0 = p0.y + (float)j0 + 0.5f*ah0;
    float pa0 = aw0 * ah0;

    float aw1 = p1.z * anc[a1][0], ah1 = p1.w * anc[a1][1];
    float qx1_1 = p1.x + (float)i1 - 0.5f*aw1, qx2_1 = p1.x + (float)i1 + 0.5f*aw1;
    float qy1_1 = p1.y + (float)j1 - 0.5f*ah1, qy2_1 = p1.y + (float)j1 + 0.5f*ah1;
    float pa1 = aw1 * ah1;

    // m = max_k (1.6*inter_k - 0.6*garea_k); best_iou > 0.6 <=> m > 0.6*parea
    float m0 = -3.402823e38f, m1 = -3.402823e38f;
    #pragma unroll 4
    for (int k = 0; k < GG; k++) {
        float4 gb = gbox[k];
        float th  = thr06[k];
        {
            float lx = fmaxf(qx1_0, gb.x), ly = fmaxf(qy1_0, gb.y);
            float rx = fminf(qx2_0, gb.z), ry = fminf(qy2_0, gb.w);
            float iw = fmaxf(rx - lx, 0.0f), ih = fmaxf(ry - ly, 0.0f);
            m0 = fmaxf(m0, fmaf(iw * ih, 1.6f, -th));
        }
        {
            float lx = fmaxf(qx1_1, gb.x), ly = fmaxf(qy1_1, gb.y);
            float rx = fminf(qx2_1, gb.z), ry = fminf(qy2_1, gb.w);
            float iw = fmaxf(rx - lx, 0.0f), ih = fmaxf(ry - ly, 0.0f);
            m1 = fmaxf(m1, fmaf(iw * ih, 1.6f, -th));
        }
    }

    #pragma unroll
    for (int sl = 0; sl < 2; sl++) {
        bool  valid = sl ? v1 : v0;
        if (!valid) continue;
        int   sidx  = sl ? s1 : s0;
        float4 p    = sl ? p1 : p0;
        float m     = sl ? m1 : m0;
        float parea = sl ? pa1 : pa0;
        float qx1 = sl ? qx1_1 : qx1_0, qx2 = sl ? qx2_1 : qx2_0;
        float qy1 = sl ? qy1_1 : qy1_0, qy2 = sl ? qy2_1 : qy2_0;

        float ipv = ip[sidx];
        int   g   = (int)selmap[sidx];

        if (g < 0) {
            float d0 = 0.01f*(p.x - 0.5f);
            float d1 = 0.01f*(p.y - 0.5f);
            float d2 = 0.01f*(p.z - 1.0f);
            float d3 = 0.01f*(p.w - 1.0f);
            acc += d0*d0 + d1*d1 + d2*d2 + d3*d3;
            if (m <= 0.6f * parea) {      // best_iou <= 0.6 (scale-invariant)
                float q = ipv * ipv;
                acc += q * q;
            }
        } else {
            float4 gb = gbox[g];
            float lx = fmaxf(qx1, gb.x), ly = fmaxf(qy1, gb.y);
            float rx = fminf(qx2, gb.z), ry = fminf(qy2, gb.w);
            float iw = fmaxf(rx - lx, 0.0f), ih = fmaxf(ry - ly, 0.0f);
            float inter = iw * ih;
            float iou_t = inter / (parea + garea[g] - inter);

            float4 tv = tarv[g];
            float d0 = p.x - tv.x;
            float d1 = p.y - tv.y;
            float d2 = p.z - tv.z;
            float d3 = p.w - tv.w;
            acc += d0*d0 + d1*d1 + d2*d2 + d3*d3;

            float mm = 5.0f * (1.0f - ipv);
            float d  = ipv - iou_t;
            acc += (mm*mm) * (d*d);

            int cls = gcls[g];
            const float* srow = sp + (size_t)sidx * CC;
            #pragma unroll
            for (int c = 0; c < CC; c++) {
                float t2 = (c == cls) ? 1.0f : 0.0f;
                float dd = srow[c] - t2;
                acc += dd * dd;
            }
        }
    }

    // block reduction -> CTA partial
    #pragma unroll
    for (int off = 16; off; off >>= 1)
        acc += __shfl_down_sync(0xffffffffu, acc, off);
    if ((tid & 31) == 0) red[tid >> 5] = acc;
    __syncthreads();

    // O(1)-tail epilogue: single global accumulator + ticket; no block-wide wait
    if (tid == 0) {
        float v = red[0] + red[1] + red[2] + red[3];
        atomicAdd(&g_sum, v);
        __threadfence();
        unsigned ticket = atomicInc(&g_ticket, GRID - 1);  // wraps to 0 after last
        if (ticket == GRID - 1) {
            float total = atomicAdd(&g_sum, 0.0f);  // RMW: observes all prior adds
            *out = total * (1.0f / (float)GG);
            __threadfence();
            g_sum = 0.0f;                           // reset for next graph replay
        }
    }
}

extern "C" void kernel_launch(void* const* d_in, const int* in_sizes, int n_in,
                              void* d_out, int out_size)
{
    const float* bbox    = (const float*)d_in[0];
    const float* iou     = (const float*)d_in[1];
    const float* score   = (const float*)d_in[2];
    const float* targets = (const float*)d_in[3];
    const float* anchors = (const float*)d_in[4];
    float* out = (float*)d_out;

    yolo_loss_kernel<<<GRID, NTHREADS>>>(bbox, iou, score, targets, anchors, out);
}

// round 13
// speedup vs baseline: 1.5319x; 1.5319x over previous
#include <cuda_runtime.h>
#include <cuda_fp16.h>

#define SS 17
#define AA 5
#define CC 20
#define BIMG 256
#define GG 32
#define HW (SS*SS)          // 289
#define NPA (HW*AA)         // 1445
#define NTHREADS 128
#define NWARPS (NTHREADS/32)
#define SPLIT 6             // CTAs per image
#define GRID (BIMG*SPLIT)   // 1536
#define CHUNK ((NPA + SPLIT - 1) / SPLIT)   // 241 (<= 2*NTHREADS: two slots/thread)

__global__ void zero_out_kernel(float* out) { *out = 0.0f; }

struct __align__(16) GTH { __half2 g1, g2, nt, pad; };  // one LDS.128 per GT

__global__ __launch_bounds__(NTHREADS, 8)
void yolo_loss_kernel(const float* __restrict__ bbox_pred,
                      const float* __restrict__ iou_pred,
                      const float* __restrict__ score_pred,
                      const float* __restrict__ targets,
                      const float* __restrict__ anchors,
                      float* __restrict__ out)
{
    const int blk  = blockIdx.x;
    const int b    = blk / SPLIT;
    const int part = blk - b * SPLIT;
    const int tid  = threadIdx.x;

    __shared__ float4 gbox[GG];      // GT corners in cell units (x17), fp32 (rare path)
    __shared__ float  garea[GG];     // (17w)*(17h)
    __shared__ GTH    gth[GG];       // half2: {g1=(x1,y1), g2=(x2,y2), nt={-0.6*ga}x2}
    __shared__ float4 tarv[GG];      // off_x, off_y, w, h (original units)
    __shared__ int    gcls[GG];
    __shared__ short  selmap[NPA];
    __shared__ float  anc[AA][2];    // anchors / 17
    __shared__ float  red[NWARPS];

    const int start = part * CHUNK;
    const int end   = (start + CHUNK < NPA) ? start + CHUNK : NPA;

    for (int i = start + tid; i < end; i += NTHREADS) selmap[i] = -1;
    if (tid < AA) {
        anc[tid][0] = anchors[tid*2+0] / 17.0f;
        anc[tid][1] = anchors[tid*2+1] / 17.0f;
    }
    __syncthreads();

    if (tid < GG) {
        const float* t = targets + ((size_t)b*GG + tid)*6;
        int   cls = (int)t[1];
        float x1 = t[2], y1 = t[3], x2 = t[4], y2 = t[5];
        gbox[tid] = make_float4(x1*17.0f, y1*17.0f, x2*17.0f, y2*17.0f);
        float w = x2 - x1, h = y2 - y1;
        float ar17 = (17.0f*w) * (17.0f*h);
        garea[tid] = ar17;
        gth[tid].g1 = __floats2half2_rn(x1*17.0f, y1*17.0f);
        gth[tid].g2 = __floats2half2_rn(x2*17.0f, y2*17.0f);
        gth[tid].nt = __half2half2(__float2half_rn(-0.6f * ar17));
        gth[tid].pad = __float2half2_rn(0.0f);
        float cxs = (x1 + x2) * 0.5f * 17.0f;
        float cys = (y1 + y2) * 0.5f * 17.0f;
        int ci = (int)floorf(cxs), cj = (int)floorf(cys);
        tarv[tid] = make_float4(cxs - (float)ci, cys - (float)cj, w, h);
        gcls[tid] = cls;
        // anchor argmax (first-max tiebreak)
        int best_a = 0; float best = -1.0f;
        float ar = w * h;
        #pragma unroll
        for (int a = 0; a < AA; a++) {
            float aw = anc[a][0], ah = anc[a][1];
            float inter = fminf(aw, w) * fminf(ah, h);
            float aiou  = inter / (aw*ah + ar - inter);
            if (aiou > best) { best = aiou; best_a = a; }
        }
        int cell = ci * SS + cj;
        selmap[cell*AA + best_a] = (short)tid;  // out-of-range writes never read
    }
    __syncthreads();

    const float* bb = bbox_pred  + (size_t)b * NPA * 4;
    const float* ip = iou_pred   + (size_t)b * NPA;
    const float* sp = score_pred + (size_t)b * NPA * CC;

    float acc = 0.0f;

    // two slots per thread, straight-line
    int  idx0 = start + tid;
    int  idx1 = start + NTHREADS + tid;
    bool v0 = idx0 < end;
    bool v1 = idx1 < end;
    int  s0 = v0 ? idx0 : start;
    int  s1 = v1 ? idx1 : start;

    float4 p0 = reinterpret_cast<const float4*>(bb)[s0];
    float4 p1 = reinterpret_cast<const float4*>(bb)[s1];

    float pa0, pa1;
    __half2 Q1_0, Q2_0, Q1_1, Q2_1;
    {
        int hw0 = s0 / AA, a0 = s0 - hw0*AA, i0 = hw0 / SS, j0 = hw0 - i0*SS;
        float aw = p0.z * anc[a0][0], ah = p0.w * anc[a0][1];
        float qx1 = p0.x + (float)i0 - 0.5f*aw, qx2 = p0.x + (float)i0 + 0.5f*aw;
        float qy1 = p0.y + (float)j0 - 0.5f*ah, qy2 = p0.y + (float)j0 + 0.5f*ah;
        Q1_0 = __floats2half2_rn(qx1, qy1);
        Q2_0 = __floats2half2_rn(qx2, qy2);
        pa0 = aw * ah;
    }
    {
        int hw1 = s1 / AA, a1 = s1 - hw1*AA, i1 = hw1 / SS, j1 = hw1 - i1*SS;
        float aw = p1.z * anc[a1][0], ah = p1.w * anc[a1][1];
        float qx1 = p1.x + (float)i1 - 0.5f*aw, qx2 = p1.x + (float)i1 + 0.5f*aw;
        float qy1 = p1.y + (float)j1 - 0.5f*ah, qy2 = p1.y + (float)j1 + 0.5f*ah;
        Q1_1 = __floats2half2_rn(qx1, qy1);
        Q2_1 = __floats2half2_rn(qx2, qy2);
        pa1 = aw * ah;
    }

    // packed predicate loop: m = max_k (1.6*inter_k - 0.6*ga_k); best_iou>0.6 <=> m>0.6*pa
    const __half2 zero2 = __float2half2_rn(0.0f);
    const __half2 c16   = __float2half2_rn(1.6f);
    __half2 m01 = __half2half2(__float2half_rn(-65504.0f));
    #pragma unroll 4
    for (int k = 0; k < GG; k++) {
        GTH g = gth[k];
        __half2 w0 = __hmax2(__hsub2(__hmin2(Q2_0, g.g2), __hmax2(Q1_0, g.g1)), zero2);
        __half2 w1 = __hmax2(__hsub2(__hmin2(Q2_1, g.g2), __hmax2(Q1_1, g.g1)), zero2);
        __half i0 = __hmul(__low2half(w0), __high2half(w0));
        __half i1 = __hmul(__low2half(w1), __high2half(w1));
        m01 = __hmax2(m01, __hfma2(__halves2half2(i0, i1), c16, g.nt));
    }
    float m0f = __half2float(__low2half(m01));
    float m1f = __half2float(__high2half(m01));

    #pragma unroll
    for (int sl = 0; sl < 2; sl++) {
        bool  valid = sl ? v1 : v0;
        if (!valid) continue;
        int   sidx  = sl ? s1 : s0;
        float4 p    = sl ? p1 : p0;
        float m     = sl ? m1f : m0f;
        float parea = sl ? pa1 : pa0;

        float ipv = ip[sidx];
        int   g   = (int)selmap[sidx];

        if (g < 0) {
            float d0 = 0.01f*(p.x - 0.5f);
            float d1 = 0.01f*(p.y - 0.5f);
            float d2 = 0.01f*(p.z - 1.0f);
            float d3 = 0.01f*(p.w - 1.0f);
            acc += d0*d0 + d1*d1 + d2*d2 + d3*d3;
            if (m <= 0.6f * parea) {      // best_iou <= 0.6
                float q = ipv * ipv;
                acc += q * q;
            }
        } else {
            // rare path: recompute fp32 corners, exact IoU with matched GT
            int hw = sidx / AA, a = sidx - hw*AA, ii = hw / SS, jj = hw - ii*SS;
            float aw = p.z * anc[a][0], ah = p.w * anc[a][1];
            float qx1 = p.x + (float)ii - 0.5f*aw, qx2 = p.x + (float)ii + 0.5f*aw;
            float qy1 = p.y + (float)jj - 0.5f*ah, qy2 = p.y + (float)jj + 0.5f*ah;

            float4 gb = gbox[g];
            float lx = fmaxf(qx1, gb.x), ly = fmaxf(qy1, gb.y);
            float rx = fminf(qx2, gb.z), ry = fminf(qy2, gb.w);
            float iw = fmaxf(rx - lx, 0.0f), ih = fmaxf(ry - ly, 0.0f);
            float inter = iw * ih;
            float iou_t = inter / (parea + garea[g] - inter);

            float4 tv = tarv[g];
            float d0 = p.x - tv.x;
            float d1 = p.y - tv.y;
            float d2 = p.z - tv.z;
            float d3 = p.w - tv.w;
            acc += d0*d0 + d1*d1 + d2*d2 + d3*d3;

            float mm = 5.0f * (1.0f - ipv);
            float d  = ipv - iou_t;
            acc += (mm*mm) * (d*d);

            int cls = gcls[g];
            const float* srow = sp + (size_t)sidx * CC;
            #pragma unroll
            for (int c = 0; c < CC; c++) {
                float t2 = (c == cls) ? 1.0f : 0.0f;
                float dd = srow[c] - t2;
                acc += dd * dd;
            }
        }
    }

    // block reduction -> atomicAdd (R8's measured-best epilogue)
    #pragma unroll
    for (int off = 16; off; off >>= 1)
        acc += __shfl_down_sync(0xffffffffu, acc, off);
    if ((tid & 31) == 0) red[tid >> 5] = acc;
    __syncthreads();
    if (tid < NWARPS) {
        float v = red[tid];
        #pragma unroll
        for (int off = (NWARPS/2); off; off >>= 1)
            v += __shfl_down_sync(0xffffffffu, v, off);
        if (tid == 0) atomicAdd(out, v * (1.0f / (float)GG));
    }
}

extern "C" void kernel_launch(void* const* d_in, const int* in_sizes, int n_in,
                              void* d_out, int out_size)
{
    const float* bbox    = (const float*)d_in[0];
    const float* iou     = (const float*)d_in[1];
    const float* score   = (const float*)d_in[2];
    const float* targets = (const float*)d_in[3];
    const float* anchors = (const float*)d_in[4];
    float* out = (float*)d_out;

    zero_out_kernel<<<1, 1>>>(out);
    yolo_loss_kernel<<<GRID, NTHREADS>>>(bbox, iou, score, targets, anchors, out);
}

// round 14
// speedup vs baseline: 1.8045x; 1.1779x over previous
#include <cuda_runtime.h>
#include <cuda_fp16.h>

#define SS 17
#define AA 5
#define CC 20
#define BIMG 256
#define GG 32
#define HW (SS*SS)          // 289
#define NPA (HW*AA)         // 1445
#define NTHREADS 128
#define NWARPS (NTHREADS/32)
#define SPLIT 4             // CTAs per image
#define GRID (BIMG*SPLIT)   // 1024  (single wave at 8 CTAs/SM)
#define CHUNK ((NPA + SPLIT - 1) / SPLIT)   // 362 (<= 3*NTHREADS: three slots/thread)

__global__ void zero_out_kernel(float* out) { *out = 0.0f; }

struct __align__(16) GTH { __half2 g1, g2, nt, pad; };  // one LDS.128 per GT

__global__ __launch_bounds__(NTHREADS, 8)
void yolo_loss_kernel(const float* __restrict__ bbox_pred,
                      const float* __restrict__ iou_pred,
                      const float* __restrict__ score_pred,
                      const float* __restrict__ targets,
                      const float* __restrict__ anchors,
                      float* __restrict__ out)
{
    const int blk  = blockIdx.x;
    const int b    = blk / SPLIT;
    const int part = blk - b * SPLIT;
    const int tid  = threadIdx.x;

    __shared__ float4 gbox[GG];      // GT corners in cell units (x17), fp32 (rare path)
    __shared__ float  garea[GG];     // (17w)*(17h)
    __shared__ GTH    gth[GG];       // half2: {g1=(x1,y1), g2=(x2,y2), nt={-0.6*ga}x2}
    __shared__ float4 tarv[GG];      // off_x, off_y, w, h (original units)
    __shared__ int    gcls[GG];
    __shared__ short  selmap[NPA];
    __shared__ float  anc[AA][2];    // anchors / 17
    __shared__ float  red[NWARPS];

    const int start = part * CHUNK;
    const int end   = (start + CHUNK < NPA) ? start + CHUNK : NPA;

    for (int i = start + tid; i < end; i += NTHREADS) selmap[i] = -1;
    if (tid < AA) {
        anc[tid][0] = anchors[tid*2+0] / 17.0f;
        anc[tid][1] = anchors[tid*2+1] / 17.0f;
    }
    __syncthreads();

    if (tid < GG) {
        const float* t = targets + ((size_t)b*GG + tid)*6;
        int   cls = (int)t[1];
        float x1 = t[2], y1 = t[3], x2 = t[4], y2 = t[5];
        gbox[tid] = make_float4(x1*17.0f, y1*17.0f, x2*17.0f, y2*17.0f);
        float w = x2 - x1, h = y2 - y1;
        float ar17 = (17.0f*w) * (17.0f*h);
        garea[tid] = ar17;
        gth[tid].g1 = __floats2half2_rn(x1*17.0f, y1*17.0f);
        gth[tid].g2 = __floats2half2_rn(x2*17.0f, y2*17.0f);
        gth[tid].nt = __half2half2(__float2half_rn(-0.6f * ar17));
        gth[tid].pad = __float2half2_rn(0.0f);
        float cxs = (x1 + x2) * 0.5f * 17.0f;
        float cys = (y1 + y2) * 0.5f * 17.0f;
        int ci = (int)floorf(cxs), cj = (int)floorf(cys);
        tarv[tid] = make_float4(cxs - (float)ci, cys - (float)cj, w, h);
        gcls[tid] = cls;
        // anchor argmax (first-max tiebreak)
        int best_a = 0; float best = -1.0f;
        float ar = w * h;
        #pragma unroll
        for (int a = 0; a < AA; a++) {
            float aw = anc[a][0], ah = anc[a][1];
            float inter = fminf(aw, w) * fminf(ah, h);
            float aiou  = inter / (aw*ah + ar - inter);
            if (aiou > best) { best = aiou; best_a = a; }
        }
        int cell = ci * SS + cj;
        selmap[cell*AA + best_a] = (short)tid;  // out-of-range writes never read
    }
    __syncthreads();

    const float* bb = bbox_pred  + (size_t)b * NPA * 4;
    const float* ip = iou_pred   + (size_t)b * NPA;
    const float* sp = score_pred + (size_t)b * NPA * CC;

    float acc = 0.0f;

    // three slots per thread, straight-line
    int  idx0 = start + tid;
    bool v0 = idx0 < end;
    bool v1 = idx0 + NTHREADS < end;
    bool v2 = idx0 + 2*NTHREADS < end;
    int  s0 = v0 ? idx0 : start;
    int  s1 = v1 ? idx0 + NTHREADS : start;
    int  s2 = v2 ? idx0 + 2*NTHREADS : start;

    float4 p0 = reinterpret_cast<const float4*>(bb)[s0];
    float4 p1 = reinterpret_cast<const float4*>(bb)[s1];
    float4 p2 = reinterpret_cast<const float4*>(bb)[s2];

    float pa0, pa1, pa2;
    __half2 Q1_0, Q2_0, Q1_1, Q2_1, Q1_2, Q2_2;
    {
        int hw = s0 / AA, a = s0 - hw*AA, ii = hw / SS, jj = hw - ii*SS;
        float aw = p0.z * anc[a][0], ah = p0.w * anc[a][1];
        Q1_0 = __floats2half2_rn(p0.x + (float)ii - 0.5f*aw, p0.y + (float)jj - 0.5f*ah);
        Q2_0 = __floats2half2_rn(p0.x + (float)ii + 0.5f*aw, p0.y + (float)jj + 0.5f*ah);
        pa0 = aw * ah;
    }
    {
        int hw = s1 / AA, a = s1 - hw*AA, ii = hw / SS, jj = hw - ii*SS;
        float aw = p1.z * anc[a][0], ah = p1.w * anc[a][1];
        Q1_1 = __floats2half2_rn(p1.x + (float)ii - 0.5f*aw, p1.y + (float)jj - 0.5f*ah);
        Q2_1 = __floats2half2_rn(p1.x + (float)ii + 0.5f*aw, p1.y + (float)jj + 0.5f*ah);
        pa1 = aw * ah;
    }
    {
        int hw = s2 / AA, a = s2 - hw*AA, ii = hw / SS, jj = hw - ii*SS;
        float aw = p2.z * anc[a][0], ah = p2.w * anc[a][1];
        Q1_2 = __floats2half2_rn(p2.x + (float)ii - 0.5f*aw, p2.y + (float)jj - 0.5f*ah);
        Q2_2 = __floats2half2_rn(p2.x + (float)ii + 0.5f*aw, p2.y + (float)jj + 0.5f*ah);
        pa2 = aw * ah;
    }

    // packed predicate loop: m = max_k (1.6*inter_k - 0.6*ga_k); best_iou>0.6 <=> m>0.6*pa
    const __half2 zero2 = __float2half2_rn(0.0f);
    const __half2 c16   = __float2half2_rn(1.6f);
    __half2 m01 = __half2half2(__float2half_rn(-65504.0f));
    __half2 m22 = m01;
    #pragma unroll 4
    for (int k = 0; k < GG; k++) {
        GTH g = gth[k];
        __half2 w0 = __hmax2(__hsub2(__hmin2(Q2_0, g.g2), __hmax2(Q1_0, g.g1)), zero2);
        __half2 w1 = __hmax2(__hsub2(__hmin2(Q2_1, g.g2), __hmax2(Q1_1, g.g1)), zero2);
        __half2 w2 = __hmax2(__hsub2(__hmin2(Q2_2, g.g2), __hmax2(Q1_2, g.g1)), zero2);
        __half i0 = __hmul(__low2half(w0), __high2half(w0));
        __half i1 = __hmul(__low2half(w1), __high2half(w1));
        __half i2 = __hmul(__low2half(w2), __high2half(w2));
        m01 = __hmax2(m01, __hfma2(__halves2half2(i0, i1), c16, g.nt));
        m22 = __hmax2(m22, __hfma2(__half2half2(i2),       c16, g.nt));
    }
    float mf[3];
    mf[0] = __half2float(__low2half(m01));
    mf[1] = __half2float(__high2half(m01));
    mf[2] = __half2float(__low2half(m22));

    #pragma unroll
    for (int sl = 0; sl < 3; sl++) {
        bool valid = (sl == 0) ? v0 : (sl == 1) ? v1 : v2;
        if (!valid) continue;
        int    sidx  = (sl == 0) ? s0 : (sl == 1) ? s1 : s2;
        float4 p     = (sl == 0) ? p0 : (sl == 1) ? p1 : p2;
        float  m     = mf[sl];
        float  parea = (sl == 0) ? pa0 : (sl == 1) ? pa1 : pa2;

        float ipv = ip[sidx];
        int   g   = (int)selmap[sidx];

        if (g < 0) {
            float d0 = 0.01f*(p.x - 0.5f);
            float d1 = 0.01f*(p.y - 0.5f);
            float d2 = 0.01f*(p.z - 1.0f);
            float d3 = 0.01f*(p.w - 1.0f);
            acc += d0*d0 + d1*d1 + d2*d2 + d3*d3;
            if (m <= 0.6f * parea) {      // best_iou <= 0.6
                float q = ipv * ipv;
                acc += q * q;
            }
        } else {
            // rare path: recompute fp32 corners, exact IoU with matched GT
            int hw = sidx / AA, a = sidx - hw*AA, ii = hw / SS, jj = hw - ii*SS;
            float aw = p.z * anc[a][0], ah = p.w * anc[a][1];
            float qx1 = p.x + (float)ii - 0.5f*aw, qx2 = p.x + (float)ii + 0.5f*aw;
            float qy1 = p.y + (float)jj - 0.5f*ah, qy2 = p.y + (float)jj + 0.5f*ah;

            float4 gb = gbox[g];
            float lx = fmaxf(qx1, gb.x), ly = fmaxf(qy1, gb.y);
            float rx = fminf(qx2, gb.z), ry = fminf(qy2, gb.w);
            float iw = fmaxf(rx - lx, 0.0f), ih = fmaxf(ry - ly, 0.0f);
            float inter = iw * ih;
            float iou_t = inter / (parea + garea[g] - inter);

            float4 tv = tarv[g];
            float d0 = p.x - tv.x;
            float d1 = p.y - tv.y;
            float d2 = p.z - tv.z;
            float d3 = p.w - tv.w;
            acc += d0*d0 + d1*d1 + d2*d2 + d3*d3;

            float mm = 5.0f * (1.0f - ipv);
            float d  = ipv - iou_t;
            acc += (mm*mm) * (d*d);

            int cls = gcls[g];
            const float* srow = sp + (size_t)sidx * CC;
            #pragma unroll
            for (int c = 0; c < CC; c++) {
                float t2 = (c == cls) ? 1.0f : 0.0f;
                float dd = srow[c] - t2;
                acc += dd * dd;
            }
        }
    }

    // block reduction -> atomicAdd (measured-best epilogue)
    #pragma unroll
    for (int off = 16; off; off >>= 1)
        acc += __shfl_down_sync(0xffffffffu, acc, off);
    if ((tid & 31) == 0) red[tid >> 5] = acc;
    __syncthreads();
    if (tid < NWARPS) {
        float v = red[tid];
        #pragma unroll
        for (int off = (NWARPS/2); off; off >>= 1)
            v += __shfl_down_sync(0xffffffffu, v, off);
        if (tid == 0) atomicAdd(out, v * (1.0f / (float)GG));
    }
}

extern "C" void kernel_launch(void* const* d_in, const int* in_sizes, int n_in,
                              void* d_out, int out_size)
{
    const float* bbox    = (const float*)d_in[0];
    const float* iou     = (const float*)d_in[1];
    const float* score   = (const float*)d_in[2];
    const float* targets = (const float*)d_in[3];
    const float* anchors = (const float*)d_in[4];
    float* out = (float*)d_out;

    zero_out_kernel<<<1, 1>>>(out);
    yolo_loss_kernel<<<GRID, NTHREADS>>>(bbox, iou, score, targets, anchors, out);
}